// round 3
// baseline (speedup 1.0000x reference)
#include <cuda_runtime.h>
#include <cuda_bf16.h>

// Problem dims
#define B_    256
#define T_    1000
#define F_    64
#define H1_   256
#define H2_   128
#define NCLS_ 5
#define DMLP_ 128

// Persistent-kernel config: 8 groups x 16 CTAs = 128 CTAs (all co-resident on 148 SMs)
#define NG    8
#define CPG   16
#define NB    32          // batch rows per group
#define NTH   256         // threads per CTA

// Padded smem strides (floats) -> bank-conflict-free LDS.64 (stride mod 32 == 2)
#define SW1X_S 66
#define SW1H_S 258
#define SW2X_S 258
#define SW2H_S 130
#define SX_S   66
#define SH1_S  258
#define SH2_S  130

#define SMEM_FLOATS (64*SW1X_S + 64*SW1H_S + 32*SW2X_S + 32*SW2H_S + 32*SX_S + 32*SH1_S + 32*SH2_S + 64 + 32 + 512 + 256)
#define SMEM_BYTES  (SMEM_FLOATS * 4)

typedef unsigned long long u64t;

// Cross-kernel / cross-CTA scratch (allowed: __device__ globals)
__device__ float    g_h1[B_ * H1_];
__device__ float    g_h2[B_ * H2_];
__device__ unsigned g_cnt[NG];
__device__ unsigned g_done[NG];

// ---- helpers ----
__device__ __forceinline__ u64t ffma2(u64t a, u64t b, u64t c) {
    u64t d;
    asm("fma.rn.f32x2 %0, %1, %2, %3;" : "=l"(d) : "l"(a), "l"(b), "l"(c));
    return d;
}
__device__ __forceinline__ float hadd2(u64t d) {
    return __uint_as_float((unsigned)(d & 0xffffffffull)) +
           __uint_as_float((unsigned)(d >> 32));
}
__device__ __forceinline__ float sigm(float x)  { return 1.0f / (1.0f + __expf(-x)); }
__device__ __forceinline__ float tanh_(float x) { return 1.0f - 2.0f / (1.0f + __expf(2.0f * x)); }

extern __shared__ float smem[];

__global__ void __launch_bounds__(NTH, 1) lstm_persistent(
    const float* __restrict__ x,
    const float* __restrict__ Wih1, const float* __restrict__ Whh1,
    const float* __restrict__ bih1, const float* __restrict__ bhh1,
    const float* __restrict__ Wih2, const float* __restrict__ Whh2,
    const float* __restrict__ bih2, const float* __restrict__ bhh2)
{
    const int tid   = threadIdx.x;
    const int grp   = blockIdx.x / CPG;
    const int lrank = blockIdx.x % CPG;
    const int b0    = grp * NB;
    const int u0    = lrank * 16;   // layer-1 hidden units owned by this CTA
    const int v0    = lrank * 8;    // layer-2 hidden units owned by this CTA

    float* sW1x = smem;                      // [64][66]
    float* sW1h = sW1x + 64 * SW1X_S;        // [64][258]
    float* sW2x = sW1h + 64 * SW1H_S;        // [32][258]
    float* sW2h = sW2x + 32 * SW2X_S;        // [32][130]
    float* sx   = sW2h + 32 * SW2H_S;        // [32][66]
    float* sh1  = sx   + 32 * SX_S;          // [32][258]
    float* sh2  = sh1  + 32 * SH1_S;         // [32][130]
    float* sb1  = sh2  + 32 * SH2_S;         // [64]
    float* sb2  = sb1  + 64;                 // [32]
    float* sc1  = sb2  + 32;                 // [32][16]
    float* sc2  = sc1  + 512;                // [32][8]

    // ---- one-time weight load into SMEM (rows = 4 gates x owned units) ----
    for (int idx = tid; idx < 64 * 64; idx += NTH) {
        int lr = idx >> 6, k = idx & 63;
        int gi = lr >> 4, uu = lr & 15;
        sW1x[lr * SW1X_S + k] = Wih1[(gi * H1_ + u0 + uu) * F_ + k];
    }
    for (int idx = tid; idx < 64 * 256; idx += NTH) {
        int lr = idx >> 8, k = idx & 255;
        int gi = lr >> 4, uu = lr & 15;
        sW1h[lr * SW1H_S + k] = Whh1[(gi * H1_ + u0 + uu) * H1_ + k];
    }
    for (int idx = tid; idx < 32 * 256; idx += NTH) {
        int lr = idx >> 8, k = idx & 255;
        int gi = lr >> 3, vv = lr & 7;
        sW2x[lr * SW2X_S + k] = Wih2[(gi * H2_ + v0 + vv) * H1_ + k];
    }
    for (int idx = tid; idx < 32 * 128; idx += NTH) {
        int lr = idx >> 7, k = idx & 127;
        int gi = lr >> 3, vv = lr & 7;
        sW2h[lr * SW2H_S + k] = Whh2[(gi * H2_ + v0 + vv) * H2_ + k];
    }
    if (tid < 64) {
        int gi = tid >> 4, uu = tid & 15;
        int r = gi * H1_ + u0 + uu;
        sb1[tid] = bih1[r] + bhh1[r];
    } else if (tid < 96) {
        int q = tid - 64;
        int gi = q >> 3, vv = q & 7;
        int r = gi * H2_ + v0 + vv;
        sb2[q] = bih2[r] + bhh2[r];
    }
    // zero state
    for (int idx = tid; idx < 32 * SH1_S; idx += NTH) sh1[idx] = 0.f;
    for (int idx = tid; idx < 512; idx += NTH) sc1[idx] = 0.f;
    sc2[tid] = 0.f;  // 256 entries, 256 threads
    {   // zero own slice of g_h2 (needed as h2(t=-1) by P2 at t=0, read after barrier 1)
        int bloc = tid >> 3, vv = tid & 7;
        __stcg(&g_h2[(b0 + bloc) * H2_ + v0 + vv], 0.f);
    }
    __syncthreads();

    unsigned bseq = 0;

    for (int t = 0; t < T_; t++) {
        // ---- stage x_t into SMEM (8-byte transfers) ----
        for (int idx = tid; idx < 32 * 32; idx += NTH) {
            int bloc = idx >> 5, kk = idx & 31;
            *(u64t*)(sx + bloc * SX_S + 2 * kk) =
                __ldg((const u64t*)(x + ((size_t)(b0 + bloc) * T_ + t) * F_ + 2 * kk));
        }
        __syncthreads();

        // ==== P1: layer-1 gates (K = 64 + 256) + c1/h1 update ====
        {
            const int uu = tid & 15, bp = tid >> 4;
            const int bA = bp * 2, bB = bA + 1;
            u64t a00 = 0, a01 = 0, a02 = 0, a03 = 0;
            u64t a10 = 0, a11 = 0, a12 = 0, a13 = 0;

            {   // x-projection part (K=64)
                const u64t* pa0 = (const u64t*)(sx + bA * SX_S);
                const u64t* pa1 = (const u64t*)(sx + bB * SX_S);
                const u64t* pw0 = (const u64t*)(sW1x + (uu)      * SW1X_S);
                const u64t* pw1 = (const u64t*)(sW1x + (16 + uu) * SW1X_S);
                const u64t* pw2 = (const u64t*)(sW1x + (32 + uu) * SW1X_S);
                const u64t* pw3 = (const u64t*)(sW1x + (48 + uu) * SW1X_S);
                #pragma unroll 8
                for (int kk = 0; kk < 32; kk++) {
                    u64t v0d = pa0[kk], v1d = pa1[kk];
                    u64t w0 = pw0[kk], w1 = pw1[kk], w2 = pw2[kk], w3 = pw3[kk];
                    a00 = ffma2(v0d, w0, a00); a10 = ffma2(v1d, w0, a10);
                    a01 = ffma2(v0d, w1, a01); a11 = ffma2(v1d, w1, a11);
                    a02 = ffma2(v0d, w2, a02); a12 = ffma2(v1d, w2, a12);
                    a03 = ffma2(v0d, w3, a03); a13 = ffma2(v1d, w3, a13);
                }
            }
            {   // recurrent part (K=256)
                const u64t* pa0 = (const u64t*)(sh1 + bA * SH1_S);
                const u64t* pa1 = (const u64t*)(sh1 + bB * SH1_S);
                const u64t* pw0 = (const u64t*)(sW1h + (uu)      * SW1H_S);
                const u64t* pw1 = (const u64t*)(sW1h + (16 + uu) * SW1H_S);
                const u64t* pw2 = (const u64t*)(sW1h + (32 + uu) * SW1H_S);
                const u64t* pw3 = (const u64t*)(sW1h + (48 + uu) * SW1H_S);
                #pragma unroll 8
                for (int kk = 0; kk < 128; kk++) {
                    u64t v0d = pa0[kk], v1d = pa1[kk];
                    u64t w0 = pw0[kk], w1 = pw1[kk], w2 = pw2[kk], w3 = pw3[kk];
                    a00 = ffma2(v0d, w0, a00); a10 = ffma2(v1d, w0, a10);
                    a01 = ffma2(v0d, w1, a01); a11 = ffma2(v1d, w1, a11);
                    a02 = ffma2(v0d, w2, a02); a12 = ffma2(v1d, w2, a12);
                    a03 = ffma2(v0d, w3, a03); a13 = ffma2(v1d, w3, a13);
                }
            }
            float bi = sb1[uu], bf = sb1[16 + uu], bg = sb1[32 + uu], bo = sb1[48 + uu];
            {   // batch bA
                float ii = sigm(hadd2(a00) + bi);
                float ff = sigm(hadd2(a01) + bf);
                float gg = tanh_(hadd2(a02) + bg);
                float oo = sigm(hadd2(a03) + bo);
                float c = sc1[bA * 16 + uu];
                c = ff * c + ii * gg;
                sc1[bA * 16 + uu] = c;
                __stcg(&g_h1[(b0 + bA) * H1_ + u0 + uu], oo * tanh_(c));
            }
            {   // batch bB
                float ii = sigm(hadd2(a10) + bi);
                float ff = sigm(hadd2(a11) + bf);
                float gg = tanh_(hadd2(a12) + bg);
                float oo = sigm(hadd2(a13) + bo);
                float c = sc1[bB * 16 + uu];
                c = ff * c + ii * gg;
                sc1[bB * 16 + uu] = c;
                __stcg(&g_h1[(b0 + bB) * H1_ + u0 + uu], oo * tanh_(c));
            }
        }
        // ---- barrier 1: h1(t) complete across group ----
        bseq++;
        {
            __threadfence();
            __syncthreads();
            if (tid == 0) {
                atomicAdd(&g_cnt[grp], 1u);
                const unsigned target = (unsigned)CPG * bseq;
                while (*((volatile unsigned*)&g_cnt[grp]) < target) { }
            }
            __syncthreads();
        }

        // ---- refresh full h1(t), h2(t-1) into SMEM (L2 loads, bypass L1) ----
        for (int idx = tid; idx < 32 * 128; idx += NTH) {
            int bloc = idx >> 7, kk = idx & 127;
            *(u64t*)(sh1 + bloc * SH1_S + 2 * kk) =
                __ldcg((const u64t*)(g_h1 + (b0 + bloc) * H1_ + 2 * kk));
        }
        for (int idx = tid; idx < 32 * 64; idx += NTH) {
            int bloc = idx >> 6, kk = idx & 63;
            *(u64t*)(sh2 + bloc * SH2_S + 2 * kk) =
                __ldcg((const u64t*)(g_h2 + (b0 + bloc) * H2_ + 2 * kk));
        }
        __syncthreads();

        // ==== P2: layer-2 gates (K = 256 + 128) + c2/h2 update ====
        {
            const int vv = tid & 7, bloc = tid >> 3;
            u64t a0 = 0, a1 = 0, a2 = 0, a3 = 0;
            {
                const u64t* pa  = (const u64t*)(sh1 + bloc * SH1_S);
                const u64t* pw0 = (const u64t*)(sW2x + (vv)      * SW2X_S);
                const u64t* pw1 = (const u64t*)(sW2x + (8 + vv)  * SW2X_S);
                const u64t* pw2 = (const u64t*)(sW2x + (16 + vv) * SW2X_S);
                const u64t* pw3 = (const u64t*)(sW2x + (24 + vv) * SW2X_S);
                #pragma unroll 8
                for (int kk = 0; kk < 128; kk++) {
                    u64t a = pa[kk];
                    a0 = ffma2(a, pw0[kk], a0);
                    a1 = ffma2(a, pw1[kk], a1);
                    a2 = ffma2(a, pw2[kk], a2);
                    a3 = ffma2(a, pw3[kk], a3);
                }
            }
            {
                const u64t* pa  = (const u64t*)(sh2 + bloc * SH2_S);
                const u64t* pw0 = (const u64t*)(sW2h + (vv)      * SW2H_S);
                const u64t* pw1 = (const u64t*)(sW2h + (8 + vv)  * SW2H_S);
                const u64t* pw2 = (const u64t*)(sW2h + (16 + vv) * SW2H_S);
                const u64t* pw3 = (const u64t*)(sW2h + (24 + vv) * SW2H_S);
                #pragma unroll 8
                for (int kk = 0; kk < 64; kk++) {
                    u64t a = pa[kk];
                    a0 = ffma2(a, pw0[kk], a0);
                    a1 = ffma2(a, pw1[kk], a1);
                    a2 = ffma2(a, pw2[kk], a2);
                    a3 = ffma2(a, pw3[kk], a3);
                }
            }
            float ii = sigm(hadd2(a0) + sb2[vv]);
            float ff = sigm(hadd2(a1) + sb2[8 + vv]);
            float gg = tanh_(hadd2(a2) + sb2[16 + vv]);
            float oo = sigm(hadd2(a3) + sb2[24 + vv]);
            float c = sc2[bloc * 8 + vv];
            c = ff * c + ii * gg;
            sc2[bloc * 8 + vv] = c;
            __stcg(&g_h2[(b0 + bloc) * H2_ + v0 + vv], oo * tanh_(c));
        }
        // ---- barrier 2: h2(t) complete across group ----
        bseq++;
        {
            __threadfence();
            __syncthreads();
            if (tid == 0) {
                atomicAdd(&g_cnt[grp], 1u);
                const unsigned target = (unsigned)CPG * bseq;
                while (*((volatile unsigned*)&g_cnt[grp]) < target) { }
            }
            __syncthreads();
        }
    }

    // ---- reset group counters so every graph replay starts from a clean state ----
    if (tid == 0) {
        atomicAdd(&g_done[grp], 1u);
        if (lrank == 0) {
            while (*((volatile unsigned*)&g_done[grp]) < (unsigned)CPG) { }
            g_cnt[grp] = 0;
            __threadfence();
            g_done[grp] = 0;
            __threadfence();
        }
    }
}

// ---- MLP head: out = relu(h2T @ W1^T + b1) @ W2^T + b2 ----
__global__ void classify_k(const float* __restrict__ W1, const float* __restrict__ b1,
                           const float* __restrict__ W2, const float* __restrict__ b2,
                           float* __restrict__ out)
{
    __shared__ float z[DMLP_];
    const int b = blockIdx.x, d = threadIdx.x;
    const float* h = g_h2 + b * H2_;
    const float* w = W1 + d * H2_;
    float acc = b1[d];
    #pragma unroll 8
    for (int k = 0; k < H2_; k++) acc += h[k] * w[k];
    z[d] = fmaxf(acc, 0.f);
    __syncthreads();
    if (d < NCLS_) {
        const float* w2 = W2 + d * DMLP_;
        float a = b2[d];
        #pragma unroll 8
        for (int k = 0; k < DMLP_; k++) a += z[k] * w2[k];
        out[b * NCLS_ + d] = a;
    }
}

extern "C" void kernel_launch(void* const* d_in, const int* in_sizes, int n_in,
                              void* d_out, int out_size)
{
    const float* x    = (const float*)d_in[0];
    const float* Wih1 = (const float*)d_in[1];
    const float* Whh1 = (const float*)d_in[2];
    const float* bih1 = (const float*)d_in[3];
    const float* bhh1 = (const float*)d_in[4];
    const float* Wih2 = (const float*)d_in[5];
    const float* Whh2 = (const float*)d_in[6];
    const float* bih2 = (const float*)d_in[7];
    const float* bhh2 = (const float*)d_in[8];
    const float* W1   = (const float*)d_in[9];
    const float* b1   = (const float*)d_in[10];
    const float* W2   = (const float*)d_in[11];
    const float* b2   = (const float*)d_in[12];

    cudaFuncSetAttribute(lstm_persistent, cudaFuncAttributeMaxDynamicSharedMemorySize, SMEM_BYTES);

    lstm_persistent<<<NG * CPG, NTH, SMEM_BYTES>>>(x, Wih1, Whh1, bih1, bhh1,
                                                   Wih2, Whh2, bih2, bhh2);
    classify_k<<<B_, DMLP_>>>(W1, b1, W2, b2, (float*)d_out);
}

// round 4
// speedup vs baseline: 2.6508x; 2.6508x over previous
#include <cuda_runtime.h>
#include <cuda_bf16.h>
#include <cstdint>

// Problem dims
#define B_    256
#define T_    1000
#define F_    64
#define H1_   256
#define H2_   128
#define NCLS_ 5
#define DMLP_ 128

// Persistent-kernel config: 8 groups x 16 CTAs = 128 CTAs co-resident
#define NG    8
#define CPG   16
#define NB    32
#define NTH   256

// MMA tiling
#define NK1   40          // L1 k-steps (K=320, 8 per step)
#define NK2   48          // L2 k-steps (K=384)
#define KH1   20          // k-steps per k-half, L1
#define KH2   24          // k-steps per k-half, L2

// SMEM layout (float offsets)
#define SACT_S   452      // [batch][x(64) | h1(256) | h2(128)] stride, ≡4 mod 32
#define SRED_S   34
#define OFF_WA1  0                        // 4*NK1*32*4  = 20480
#define OFF_WA2  (OFF_WA1 + 20480)       // 2*NK2*32*4  = 12288
#define OFF_ACT  (OFF_WA2 + 12288)       // 32*452      = 14464
#define OFF_RED1 (OFF_ACT + 14464)       // 2*64*34     = 4352
#define OFF_RED2 (OFF_RED1 + 4352)       // 2*32*34     = 2176
#define OFF_B1   (OFF_RED2 + 2176)       // 64
#define OFF_B2   (OFF_B1 + 64)           // 32
#define OFF_C1   (OFF_B2 + 32)           // 32*16 = 512
#define OFF_C2   (OFF_C1 + 512)          // 32*8  = 256
#define SMEM_FLOATS (OFF_C2 + 256)
#define SMEM_BYTES  (SMEM_FLOATS * 4)

typedef unsigned long long u64t;

__device__ float    g_h1[B_ * H1_];
__device__ float    g_h2[B_ * H2_];
__device__ unsigned g_cnt[NG];
__device__ unsigned g_done[NG];

__device__ __forceinline__ unsigned f2tf(float f) {
    unsigned u;
    asm("cvt.rna.tf32.f32 %0, %1;" : "=r"(u) : "f"(f));
    return u;
}
__device__ __forceinline__ void mma8(float* d, uint4 a, unsigned b0, unsigned b1) {
    asm volatile(
        "mma.sync.aligned.m16n8k8.row.col.f32.tf32.tf32.f32 "
        "{%0,%1,%2,%3},{%4,%5,%6,%7},{%8,%9},{%0,%1,%2,%3};"
        : "+f"(d[0]), "+f"(d[1]), "+f"(d[2]), "+f"(d[3])
        : "r"(a.x), "r"(a.y), "r"(a.z), "r"(a.w), "r"(b0), "r"(b1));
}
__device__ __forceinline__ float sigm(float x)  { return 1.0f / (1.0f + __expf(-x)); }
__device__ __forceinline__ float tanh_(float x) { return 1.0f - 2.0f / (1.0f + __expf(2.0f * x)); }

extern __shared__ float smem[];

__global__ void __launch_bounds__(NTH, 1) lstm_persistent(
    const float* __restrict__ x,
    const float* __restrict__ Wih1, const float* __restrict__ Whh1,
    const float* __restrict__ bih1, const float* __restrict__ bhh1,
    const float* __restrict__ Wih2, const float* __restrict__ Whh2,
    const float* __restrict__ bih2, const float* __restrict__ bhh2)
{
    const int tid   = threadIdx.x;
    const int wid   = tid >> 5;
    const int lane  = tid & 31;
    const int grp   = blockIdx.x / CPG;
    const int lrank = blockIdx.x % CPG;
    const int b0    = grp * NB;
    const int u0    = lrank * 16;   // layer-1 units owned
    const int v0    = lrank * 8;    // layer-2 units owned

    unsigned* sWA1 = (unsigned*)(smem + OFF_WA1);
    unsigned* sWA2 = (unsigned*)(smem + OFF_WA2);
    float*    sAct = smem + OFF_ACT;
    float*    sR1  = smem + OFF_RED1;          // [2][64][34]
    float*    sR2  = smem + OFF_RED2;          // [2][32][34]
    float*    sb1  = smem + OFF_B1;
    float*    sb2  = smem + OFF_B2;
    float*    sc1  = smem + OFF_C1;            // [b][16]
    float*    sc2  = smem + OFF_C2;            // [b][8]

    // ================= init: weight swizzle into fragment-linear tf32 =================
    // A-frag element (mt, ks, lane l, reg r): row = mt*16 + (l>>2) + (r&1)*8,
    //                                         k   = ks*8 + (l&3) + ((r>>1)&1)*4
    for (int idx = tid; idx < 4 * NK1 * 32 * 4; idx += NTH) {
        int r = idx & 3, l = (idx >> 2) & 31, rest = idx >> 7;
        int ks = rest % NK1, mt = rest / NK1;
        int rl = mt * 16 + (l >> 2) + (r & 1) * 8;
        int k  = ks * 8 + (l & 3) + ((r >> 1) & 1) * 4;
        int gi = rl >> 4, uu = rl & 15;
        int grow = gi * H1_ + u0 + uu;
        float w = (k < F_) ? Wih1[grow * F_ + k] : Whh1[grow * H1_ + (k - F_)];
        sWA1[idx] = f2tf(w);
    }
    for (int idx = tid; idx < 2 * NK2 * 32 * 4; idx += NTH) {
        int r = idx & 3, l = (idx >> 2) & 31, rest = idx >> 7;
        int ks = rest % NK2, mt = rest / NK2;
        int rl = mt * 16 + (l >> 2) + (r & 1) * 8;
        int k  = ks * 8 + (l & 3) + ((r >> 1) & 1) * 4;
        int gi = rl >> 3, vv = rl & 7;
        int grow = gi * H2_ + v0 + vv;
        float w = (k < H1_) ? Wih2[grow * H1_ + k] : Whh2[grow * H2_ + (k - H1_)];
        sWA2[idx] = f2tf(w);
    }
    if (tid < 64) {
        int gi = tid >> 4, uu = tid & 15;
        int rr = gi * H1_ + u0 + uu;
        sb1[tid] = bih1[rr] + bhh1[rr];
    } else if (tid < 96) {
        int q = tid - 64;
        int gi = q >> 3, vv = q & 7;
        int rr = gi * H2_ + v0 + vv;
        sb2[q] = bih2[rr] + bhh2[rr];
    }
    for (int idx = tid; idx < 32 * SACT_S; idx += NTH) sAct[idx] = 0.f;
    for (int idx = tid; idx < 512; idx += NTH) sc1[idx] = 0.f;
    sc2[tid & 255] = 0.f;
    {   // zero own slice of g_h2 (h2(-1) = 0, read at t=0 refresh after barrier)
        int bb = tid >> 3, vv = tid & 7;
        __stcg(&g_h2[(b0 + bb) * H2_ + v0 + vv], 0.f);
    }
    __syncthreads();
    // stage x(0) (tf32-rounded)
    for (int idx = tid; idx < 32 * 32; idx += NTH) {
        int bb = idx >> 5, kk = idx & 31;
        u64t v = __ldg((const u64t*)(x + ((size_t)(b0 + bb) * T_) * F_) + kk);
        unsigned lo = f2tf(__uint_as_float((unsigned)v));
        unsigned hi = f2tf(__uint_as_float((unsigned)(v >> 32)));
        *(u64t*)(sAct + bb * SACT_S + 2 * kk) = ((u64t)hi << 32) | lo;
    }
    __syncthreads();

    // warp roles
    const int quad = wid & 3, kh = wid >> 2;
    const int qm = quad & 1, qn = quad >> 1;          // L1: mtiles 2qm,2qm+1; ntiles 2qn,2qn+1
    const int cm = wid & 1, cn = (wid >> 1) & 1;      // L2: mtile cm; ntiles 2cn,2cn+1
    const int kl = lane & 3;
    const unsigned* actu = (const unsigned*)sAct;
    const uint4* pA1a = (const uint4*)sWA1 + (2 * qm) * NK1 * 32 + lane;
    const uint4* pA1b = pA1a + NK1 * 32;
    const uint4* pA2  = (const uint4*)sWA2 + cm * NK2 * 32 + lane;
    const int n1a = ((2 * qn) * 8 + (lane >> 2)) * SACT_S + kl;       // L1 B row offsets
    const int n1b = n1a + 8 * SACT_S;
    const int n2a = ((2 * cn) * 8 + (lane >> 2)) * SACT_S + kl;       // L2 B row offsets
    const int n2b = n2a + 8 * SACT_S;

    unsigned bseq = 0;

    for (int t = 0; t <= T_; t++) {
        // ================= MMA phase =================
        if (t < T_) {   // L1: gates(t) from x(t), h1(t-1)
            float a00[4] = {0,0,0,0}, a01[4] = {0,0,0,0};
            float a10[4] = {0,0,0,0}, a11[4] = {0,0,0,0};
            const int ke = kh * KH1 + KH1;
            #pragma unroll 4
            for (int ks = kh * KH1; ks < ke; ks++) {
                uint4 A0 = pA1a[ks * 32];
                uint4 A1 = pA1b[ks * 32];
                int kb = ks * 8;
                unsigned b00 = actu[n1a + kb], b01 = actu[n1a + kb + 4];
                unsigned b10 = actu[n1b + kb], b11 = actu[n1b + kb + 4];
                mma8(a00, A0, b00, b01); mma8(a01, A0, b10, b11);
                mma8(a10, A1, b00, b01); mma8(a11, A1, b10, b11);
            }
            float* R = sR1 + kh * 64 * SRED_S;
            int r0 = (2 * qm) * 16 + (lane >> 2);
            int c0 = (2 * qn) * 8 + (lane & 3) * 2;
            *(float2*)(R + (r0     ) * SRED_S + c0    ) = make_float2(a00[0], a00[1]);
            *(float2*)(R + (r0 +  8) * SRED_S + c0    ) = make_float2(a00[2], a00[3]);
            *(float2*)(R + (r0     ) * SRED_S + c0 + 8) = make_float2(a01[0], a01[1]);
            *(float2*)(R + (r0 +  8) * SRED_S + c0 + 8) = make_float2(a01[2], a01[3]);
            *(float2*)(R + (r0 + 16) * SRED_S + c0    ) = make_float2(a10[0], a10[1]);
            *(float2*)(R + (r0 + 24) * SRED_S + c0    ) = make_float2(a10[2], a10[3]);
            *(float2*)(R + (r0 + 16) * SRED_S + c0 + 8) = make_float2(a11[0], a11[1]);
            *(float2*)(R + (r0 + 24) * SRED_S + c0 + 8) = make_float2(a11[2], a11[3]);
        }
        if (t >= 1) {   // L2: gates for h2(t-1) from h1(t-1), h2(t-2)
            float c0a[4] = {0,0,0,0}, c1a[4] = {0,0,0,0};
            const int ke = kh * KH2 + KH2;
            #pragma unroll 4
            for (int ks = kh * KH2; ks < ke; ks++) {
                uint4 A = pA2[ks * 32];
                int kb = 64 + ks * 8;    // L2 K window starts at h1 region
                unsigned b00 = actu[n2a + kb], b01 = actu[n2a + kb + 4];
                unsigned b10 = actu[n2b + kb], b11 = actu[n2b + kb + 4];
                mma8(c0a, A, b00, b01); mma8(c1a, A, b10, b11);
            }
            float* R = sR2 + kh * 32 * SRED_S;
            int r0 = cm * 16 + (lane >> 2);
            int c0 = (2 * cn) * 8 + (lane & 3) * 2;
            *(float2*)(R + (r0    ) * SRED_S + c0    ) = make_float2(c0a[0], c0a[1]);
            *(float2*)(R + (r0 + 8) * SRED_S + c0    ) = make_float2(c0a[2], c0a[3]);
            *(float2*)(R + (r0    ) * SRED_S + c0 + 8) = make_float2(c1a[0], c1a[1]);
            *(float2*)(R + (r0 + 8) * SRED_S + c0 + 8) = make_float2(c1a[2], c1a[3]);
        }
        __syncthreads();

        // ================= pointwise =================
        if (t < T_) {   // h1(t)
            const int uu = tid & 15, bq = tid >> 4;
            #pragma unroll
            for (int pass = 0; pass < 2; pass++) {
                int bb = bq + pass * 16;
                float s0 = sR1[(0  + uu) * SRED_S + bb] + sR1[64 * SRED_S + (0  + uu) * SRED_S + bb];
                float s1 = sR1[(16 + uu) * SRED_S + bb] + sR1[64 * SRED_S + (16 + uu) * SRED_S + bb];
                float s2 = sR1[(32 + uu) * SRED_S + bb] + sR1[64 * SRED_S + (32 + uu) * SRED_S + bb];
                float s3 = sR1[(48 + uu) * SRED_S + bb] + sR1[64 * SRED_S + (48 + uu) * SRED_S + bb];
                float ii = sigm(s0 + sb1[uu]);
                float ff = sigm(s1 + sb1[16 + uu]);
                float gg = tanh_(s2 + sb1[32 + uu]);
                float oo = sigm(s3 + sb1[48 + uu]);
                float c = sc1[bb * 16 + uu];
                c = ff * c + ii * gg;
                sc1[bb * 16 + uu] = c;
                float h = oo * tanh_(c);
                __stcg(&g_h1[(b0 + bb) * H1_ + u0 + uu], __uint_as_float(f2tf(h)));
            }
        }
        if (t >= 1) {   // h2(t-1)
            const int vv = tid & 7, bb = tid >> 3;
            float s0 = sR2[(0  + vv) * SRED_S + bb] + sR2[32 * SRED_S + (0  + vv) * SRED_S + bb];
            float s1 = sR2[(8  + vv) * SRED_S + bb] + sR2[32 * SRED_S + (8  + vv) * SRED_S + bb];
            float s2 = sR2[(16 + vv) * SRED_S + bb] + sR2[32 * SRED_S + (16 + vv) * SRED_S + bb];
            float s3 = sR2[(24 + vv) * SRED_S + bb] + sR2[32 * SRED_S + (24 + vv) * SRED_S + bb];
            float ii = sigm(s0 + sb2[vv]);
            float ff = sigm(s1 + sb2[8 + vv]);
            float gg = tanh_(s2 + sb2[16 + vv]);
            float oo = sigm(s3 + sb2[24 + vv]);
            float c = sc2[bb * 8 + vv];
            c = ff * c + ii * gg;
            sc2[bb * 8 + vv] = c;
            float h = oo * tanh_(c);
            __stcg(&g_h2[(b0 + bb) * H2_ + v0 + vv], __uint_as_float(f2tf(h)));
        }
        if (t == T_) break;

        // ================= group barrier (one per step) =================
        bseq++;
        __threadfence();
        __syncthreads();
        if (tid == 0) {
            atomicAdd(&g_cnt[grp], 1u);
            const unsigned target = (unsigned)CPG * bseq;
            while (*((volatile unsigned*)&g_cnt[grp]) < target) { }
        }
        __syncthreads();

        // ================= refresh sAct: h1(t), h2(t-1), x(t+1) =================
        {
            const u64t* gh1 = (const u64t*)(g_h1 + b0 * H1_);
            for (int idx = tid; idx < 32 * 128; idx += NTH) {
                int bb = idx >> 7, kk = idx & 127;
                *(u64t*)(sAct + bb * SACT_S + 64 + 2 * kk) = __ldcg(gh1 + bb * 128 + kk);
            }
            const u64t* gh2 = (const u64t*)(g_h2 + b0 * H2_);
            for (int idx = tid; idx < 32 * 64; idx += NTH) {
                int bb = idx >> 6, kk = idx & 63;
                *(u64t*)(sAct + bb * SACT_S + 320 + 2 * kk) = __ldcg(gh2 + bb * 64 + kk);
            }
            if (t + 1 < T_) {
                for (int idx = tid; idx < 32 * 32; idx += NTH) {
                    int bb = idx >> 5, kk = idx & 31;
                    u64t v = __ldg((const u64t*)(x + ((size_t)(b0 + bb) * T_ + (t + 1)) * F_) + kk);
                    unsigned lo = f2tf(__uint_as_float((unsigned)v));
                    unsigned hi = f2tf(__uint_as_float((unsigned)(v >> 32)));
                    *(u64t*)(sAct + bb * SACT_S + 2 * kk) = ((u64t)hi << 32) | lo;
                }
            }
        }
        __syncthreads();
    }

    // ---- reset group counters for the next graph replay ----
    if (tid == 0) {
        atomicAdd(&g_done[grp], 1u);
        if (lrank == 0) {
            while (*((volatile unsigned*)&g_done[grp]) < (unsigned)CPG) { }
            g_cnt[grp] = 0;
            __threadfence();
            g_done[grp] = 0;
            __threadfence();
        }
    }
}

// ---- MLP head: out = relu(h2T @ W1^T + b1) @ W2^T + b2 ----
__global__ void classify_k(const float* __restrict__ W1, const float* __restrict__ b1,
                           const float* __restrict__ W2, const float* __restrict__ b2,
                           float* __restrict__ out)
{
    __shared__ float z[DMLP_];
    const int b = blockIdx.x, d = threadIdx.x;
    const float* h = g_h2 + b * H2_;
    const float* w = W1 + d * H2_;
    float acc = b1[d];
    #pragma unroll 8
    for (int k = 0; k < H2_; k++) acc += h[k] * w[k];
    z[d] = fmaxf(acc, 0.f);
    __syncthreads();
    if (d < NCLS_) {
        const float* w2 = W2 + d * DMLP_;
        float a = b2[d];
        #pragma unroll 8
        for (int k = 0; k < DMLP_; k++) a += z[k] * w2[k];
        out[b * NCLS_ + d] = a;
    }
}

extern "C" void kernel_launch(void* const* d_in, const int* in_sizes, int n_in,
                              void* d_out, int out_size)
{
    const float* x    = (const float*)d_in[0];
    const float* Wih1 = (const float*)d_in[1];
    const float* Whh1 = (const float*)d_in[2];
    const float* bih1 = (const float*)d_in[3];
    const float* bhh1 = (const float*)d_in[4];
    const float* Wih2 = (const float*)d_in[5];
    const float* Whh2 = (const float*)d_in[6];
    const float* bih2 = (const float*)d_in[7];
    const float* bhh2 = (const float*)d_in[8];
    const float* W1   = (const float*)d_in[9];
    const float* b1   = (const float*)d_in[10];
    const float* W2   = (const float*)d_in[11];
    const float* b2   = (const float*)d_in[12];

    cudaFuncSetAttribute(lstm_persistent, cudaFuncAttributeMaxDynamicSharedMemorySize, SMEM_BYTES);

    lstm_persistent<<<NG * CPG, NTH, SMEM_BYTES>>>(x, Wih1, Whh1, bih1, bhh1,
                                                   Wih2, Whh2, bih2, bhh2);
    classify_k<<<B_, DMLP_>>>(W1, b1, W2, b2, (float*)d_out);
}

// round 5
// speedup vs baseline: 2.8559x; 1.0774x over previous
#include <cuda_runtime.h>
#include <cuda_bf16.h>
#include <cstdint>

// Problem dims
#define B_    256
#define T_    1000
#define F_    64
#define H1_   256
#define H2_   128
#define NCLS_ 5
#define DMLP_ 128

// Persistent-kernel config: 8 groups x 16 CTAs = 128 CTAs co-resident
#define NG    8
#define CPG   16
#define NB    32
#define NTH   512

// MMA tiling
#define NK1   40          // L1 k-steps (K=320, 8 per step)
#define NK2   48          // L2 k-steps (K=384)

// SMEM layout (float offsets)
#define SACT_S   452      // [batch][x(64) | h1(256) | h2(128)] stride, ≡4 mod 32
#define SRED_S   34
#define OFF_WA1  0                        // 4*NK1*32*4  = 20480
#define OFF_WA2  (OFF_WA1 + 20480)       // 2*NK2*32*4  = 12288
#define OFF_ACT  (OFF_WA2 + 12288)       // 32*452      = 14464
#define OFF_RED1 (OFF_ACT + 14464)       // 64*34       = 2176  (single copy)
#define OFF_RED2 (OFF_RED1 + 2176)       // 2*32*34     = 2176
#define OFF_B1   (OFF_RED2 + 2176)       // 64
#define OFF_B2   (OFF_B1 + 64)           // 32
#define OFF_C1   (OFF_B2 + 32)           // 32*16 = 512
#define OFF_C2   (OFF_C1 + 512)          // 32*8  = 256
#define SMEM_FLOATS (OFF_C2 + 256)
#define SMEM_BYTES  (SMEM_FLOATS * 4)

typedef unsigned long long u64t;

__device__ float    g_h1[B_ * H1_];
__device__ float    g_h2[B_ * H2_];
__device__ unsigned g_cnt[NG];
__device__ unsigned g_done[NG];

__device__ __forceinline__ unsigned f2tf(float f) {
    unsigned u;
    asm("cvt.rna.tf32.f32 %0, %1;" : "=r"(u) : "f"(f));
    return u;
}
__device__ __forceinline__ void mma8(float* d, uint4 a, unsigned b0, unsigned b1) {
    asm("mma.sync.aligned.m16n8k8.row.col.f32.tf32.tf32.f32 "
        "{%0,%1,%2,%3},{%4,%5,%6,%7},{%8,%9},{%0,%1,%2,%3};"
        : "+f"(d[0]), "+f"(d[1]), "+f"(d[2]), "+f"(d[3])
        : "r"(a.x), "r"(a.y), "r"(a.z), "r"(a.w), "r"(b0), "r"(b1));
}
__device__ __forceinline__ float tanhfast(float x) {
    float y;
    asm("tanh.approx.f32 %0, %1;" : "=f"(y) : "f"(x));
    return y;
}
__device__ __forceinline__ float sigm(float x)  { return 0.5f * tanhfast(0.5f * x) + 0.5f; }

extern __shared__ float smem[];

__global__ void __launch_bounds__(NTH, 1) lstm_persistent(
    const float* __restrict__ x,
    const float* __restrict__ Wih1, const float* __restrict__ Whh1,
    const float* __restrict__ bih1, const float* __restrict__ bhh1,
    const float* __restrict__ Wih2, const float* __restrict__ Whh2,
    const float* __restrict__ bih2, const float* __restrict__ bhh2)
{
    const int tid   = threadIdx.x;
    const int wid   = tid >> 5;
    const int lane  = tid & 31;
    const int grp   = blockIdx.x / CPG;
    const int lrank = blockIdx.x % CPG;
    const int b0    = grp * NB;
    const int u0    = lrank * 16;   // layer-1 units owned
    const int v0    = lrank * 8;    // layer-2 units owned

    unsigned* sWA1 = (unsigned*)(smem + OFF_WA1);
    unsigned* sWA2 = (unsigned*)(smem + OFF_WA2);
    float*    sAct = smem + OFF_ACT;
    float*    sR1  = smem + OFF_RED1;          // [64][34]
    float*    sR2  = smem + OFF_RED2;          // [2][32][34]
    float*    sb1  = smem + OFF_B1;
    float*    sb2  = smem + OFF_B2;
    float*    sc1  = smem + OFF_C1;            // [b][16]
    float*    sc2  = smem + OFF_C2;            // [b][8]

    // ================= init: weight swizzle into fragment-linear tf32 =================
    // A-frag element (mt, ks, lane l, reg r): row = mt*16 + (l>>2) + (r&1)*8,
    //                                         k   = ks*8 + (l&3) + ((r>>1)&1)*4
    for (int idx = tid; idx < 4 * NK1 * 32 * 4; idx += NTH) {
        int r = idx & 3, l = (idx >> 2) & 31, rest = idx >> 7;
        int ks = rest % NK1, mt = rest / NK1;
        int rl = mt * 16 + (l >> 2) + (r & 1) * 8;
        int k  = ks * 8 + (l & 3) + ((r >> 1) & 1) * 4;
        int gi = rl >> 4, uu = rl & 15;
        int grow = gi * H1_ + u0 + uu;
        float w = (k < F_) ? Wih1[grow * F_ + k] : Whh1[grow * H1_ + (k - F_)];
        sWA1[idx] = f2tf(w);
    }
    for (int idx = tid; idx < 2 * NK2 * 32 * 4; idx += NTH) {
        int r = idx & 3, l = (idx >> 2) & 31, rest = idx >> 7;
        int ks = rest % NK2, mt = rest / NK2;
        int rl = mt * 16 + (l >> 2) + (r & 1) * 8;
        int k  = ks * 8 + (l & 3) + ((r >> 1) & 1) * 4;
        int gi = rl >> 3, vv = rl & 7;
        int grow = gi * H2_ + v0 + vv;
        float w = (k < H1_) ? Wih2[grow * H1_ + k] : Whh2[grow * H2_ + (k - H1_)];
        sWA2[idx] = f2tf(w);
    }
    if (tid < 64) {
        int gi = tid >> 4, uu = tid & 15;
        int rr = gi * H1_ + u0 + uu;
        sb1[tid] = bih1[rr] + bhh1[rr];
    } else if (tid < 96) {
        int q = tid - 64;
        int gi = q >> 3, vv = q & 7;
        int rr = gi * H2_ + v0 + vv;
        sb2[q] = bih2[rr] + bhh2[rr];
    }
    for (int idx = tid; idx < 32 * SACT_S; idx += NTH) sAct[idx] = 0.f;
    for (int idx = tid; idx < 512; idx += NTH) sc1[idx] = 0.f;
    if (tid < 256) sc2[tid] = 0.f;
    if (tid < 256) {   // zero own slice of g_h2 (h2(-1)=0, read at t=0 refresh)
        int bb = tid >> 3, vv = tid & 7;
        __stcg(&g_h2[(b0 + bb) * H2_ + v0 + vv], 0.f);
    }
    __syncthreads();
    // stage x(0) (tf32-rounded)
    for (int idx = tid; idx < 32 * 32; idx += NTH) {
        int bb = idx >> 5, kk = idx & 31;
        u64t v = __ldg((const u64t*)(x + ((size_t)(b0 + bb) * T_) * F_) + kk);
        unsigned lo = f2tf(__uint_as_float((unsigned)v));
        unsigned hi = f2tf(__uint_as_float((unsigned)(v >> 32)));
        *(u64t*)(sAct + bb * SACT_S + 2 * kk) = ((u64t)hi << 32) | lo;
    }
    __syncthreads();

    // warp roles
    const int mt  = wid & 3,        nt  = wid >> 2;          // L1: 4 m-tiles x 4 n-tiles
    const int mt2 = wid & 1,        nt2 = (wid >> 1) & 3;    // L2: 2 m-tiles x 4 n-tiles
    const int kh2 = wid >> 3;                                // L2: 2 k-halves
    const unsigned* actu = (const unsigned*)sAct;
    const uint4* pA1 = (const uint4*)sWA1 + mt  * NK1 * 32 + lane;
    const uint4* pA2 = (const uint4*)sWA2 + mt2 * NK2 * 32 + lane;
    const int n1 = (nt  * 8 + (lane >> 2)) * SACT_S + (lane & 3);
    const int n2 = (nt2 * 8 + (lane >> 2)) * SACT_S + (lane & 3);

    unsigned bseq = 0;

    for (int t = 0; t <= T_; t++) {
        // ================= MMA phase =================
        if (t < T_) {   // L1: gates(t) from x(t), h1(t-1); full K per warp, 2 chains
            float dA[4] = {0,0,0,0}, dB[4] = {0,0,0,0};
            #pragma unroll 4
            for (int j = 0; j < 20; j++) {
                uint4 A0 = pA1[j * 32];
                uint4 A1 = pA1[(j + 20) * 32];
                int ka = j * 8, kb = (j + 20) * 8;
                unsigned b0a = actu[n1 + ka], b1a = actu[n1 + ka + 4];
                unsigned b0b = actu[n1 + kb], b1b = actu[n1 + kb + 4];
                mma8(dA, A0, b0a, b1a);
                mma8(dB, A1, b0b, b1b);
            }
            int r0 = mt * 16 + (lane >> 2);
            int c0 = nt * 8 + (lane & 3) * 2;
            *(float2*)(sR1 + r0 * SRED_S + c0)       = make_float2(dA[0] + dB[0], dA[1] + dB[1]);
            *(float2*)(sR1 + (r0 + 8) * SRED_S + c0) = make_float2(dA[2] + dB[2], dA[3] + dB[3]);
        }
        if (t >= 1) {   // L2: gates for h2(t-1) from h1(t-1), h2(t-2); k-half per warp
            float dA[4] = {0,0,0,0}, dB[4] = {0,0,0,0};
            const int base = kh2 * 24;
            #pragma unroll 4
            for (int j = 0; j < 12; j++) {
                uint4 A0 = pA2[(base + j) * 32];
                uint4 A1 = pA2[(base + j + 12) * 32];
                int ka = 64 + (base + j) * 8, kb = 64 + (base + j + 12) * 8;
                unsigned b0a = actu[n2 + ka], b1a = actu[n2 + ka + 4];
                unsigned b0b = actu[n2 + kb], b1b = actu[n2 + kb + 4];
                mma8(dA, A0, b0a, b1a);
                mma8(dB, A1, b0b, b1b);
            }
            float* R = sR2 + kh2 * 32 * SRED_S;
            int r0 = mt2 * 16 + (lane >> 2);
            int c0 = nt2 * 8 + (lane & 3) * 2;
            *(float2*)(R + r0 * SRED_S + c0)       = make_float2(dA[0] + dB[0], dA[1] + dB[1]);
            *(float2*)(R + (r0 + 8) * SRED_S + c0) = make_float2(dA[2] + dB[2], dA[3] + dB[3]);
        }
        __syncthreads();

        // ================= pointwise =================
        if (t < T_) {   // h1(t): 512 threads cover 16 units x 32 batches
            const int uu = tid & 15, bb = tid >> 4;
            float s0 = sR1[(0  + uu) * SRED_S + bb];
            float s1 = sR1[(16 + uu) * SRED_S + bb];
            float s2 = sR1[(32 + uu) * SRED_S + bb];
            float s3 = sR1[(48 + uu) * SRED_S + bb];
            float ii = sigm(s0 + sb1[uu]);
            float ff = sigm(s1 + sb1[16 + uu]);
            float gg = tanhfast(s2 + sb1[32 + uu]);
            float oo = sigm(s3 + sb1[48 + uu]);
            float c = sc1[bb * 16 + uu];
            c = ff * c + ii * gg;
            sc1[bb * 16 + uu] = c;
            float h = oo * tanhfast(c);
            __stcg(&g_h1[(b0 + bb) * H1_ + u0 + uu], __uint_as_float(f2tf(h)));
        }
        if (t >= 1 && tid < 256) {   // h2(t-1): 8 units x 32 batches
            const int vv = tid & 7, bb = tid >> 3;
            float s0 = sR2[(0  + vv) * SRED_S + bb] + sR2[32 * SRED_S + (0  + vv) * SRED_S + bb];
            float s1 = sR2[(8  + vv) * SRED_S + bb] + sR2[32 * SRED_S + (8  + vv) * SRED_S + bb];
            float s2 = sR2[(16 + vv) * SRED_S + bb] + sR2[32 * SRED_S + (16 + vv) * SRED_S + bb];
            float s3 = sR2[(24 + vv) * SRED_S + bb] + sR2[32 * SRED_S + (24 + vv) * SRED_S + bb];
            float ii = sigm(s0 + sb2[vv]);
            float ff = sigm(s1 + sb2[8 + vv]);
            float gg = tanhfast(s2 + sb2[16 + vv]);
            float oo = sigm(s3 + sb2[24 + vv]);
            float c = sc2[bb * 8 + vv];
            c = ff * c + ii * gg;
            sc2[bb * 8 + vv] = c;
            float h = oo * tanhfast(c);
            __stcg(&g_h2[(b0 + bb) * H2_ + v0 + vv], __uint_as_float(f2tf(h)));
        }
        if (t == T_) break;

        // ---- stage x(t+1) BEFORE the barrier (overlaps global latency w/ spin) ----
        // sAct x-region is no longer read this step (MMA done, synced above).
        if (t + 1 < T_) {
            for (int idx = tid; idx < 32 * 32; idx += NTH) {
                int bb = idx >> 5, kk = idx & 31;
                u64t v = __ldg((const u64t*)(x + ((size_t)(b0 + bb) * T_ + (t + 1)) * F_) + kk);
                unsigned lo = f2tf(__uint_as_float((unsigned)v));
                unsigned hi = f2tf(__uint_as_float((unsigned)(v >> 32)));
                *(u64t*)(sAct + bb * SACT_S + 2 * kk) = ((u64t)hi << 32) | lo;
            }
        }

        // ================= group barrier (one per step) =================
        bseq++;
        __threadfence();
        __syncthreads();
        if (tid == 0) {
            atomicAdd(&g_cnt[grp], 1u);
            const unsigned target = (unsigned)CPG * bseq;
            while (*((volatile unsigned*)&g_cnt[grp]) < target) { }
        }
        __syncthreads();

        // ================= refresh sAct: h1(t), h2(t-1) =================
        {
            const u64t* gh1 = (const u64t*)(g_h1 + b0 * H1_);
            for (int idx = tid; idx < 32 * 128; idx += NTH) {
                int bb = idx >> 7, kk = idx & 127;
                *(u64t*)(sAct + bb * SACT_S + 64 + 2 * kk) = __ldcg(gh1 + bb * 128 + kk);
            }
            const u64t* gh2 = (const u64t*)(g_h2 + b0 * H2_);
            for (int idx = tid; idx < 32 * 64; idx += NTH) {
                int bb = idx >> 6, kk = idx & 63;
                *(u64t*)(sAct + bb * SACT_S + 320 + 2 * kk) = __ldcg(gh2 + bb * 64 + kk);
            }
        }
        __syncthreads();
    }

    // ---- reset group counters for the next graph replay ----
    if (tid == 0) {
        atomicAdd(&g_done[grp], 1u);
        if (lrank == 0) {
            while (*((volatile unsigned*)&g_done[grp]) < (unsigned)CPG) { }
            g_cnt[grp] = 0;
            __threadfence();
            g_done[grp] = 0;
            __threadfence();
        }
    }
}

// ---- MLP head: out = relu(h2T @ W1^T + b1) @ W2^T + b2 ----
__global__ void classify_k(const float* __restrict__ W1, const float* __restrict__ b1,
                           const float* __restrict__ W2, const float* __restrict__ b2,
                           float* __restrict__ out)
{
    __shared__ float z[DMLP_];
    const int b = blockIdx.x, d = threadIdx.x;
    const float* h = g_h2 + b * H2_;
    const float* w = W1 + d * H2_;
    float acc = b1[d];
    #pragma unroll 8
    for (int k = 0; k < H2_; k++) acc += h[k] * w[k];
    z[d] = fmaxf(acc, 0.f);
    __syncthreads();
    if (d < NCLS_) {
        const float* w2 = W2 + d * DMLP_;
        float a = b2[d];
        #pragma unroll 8
        for (int k = 0; k < DMLP_; k++) a += z[k] * w2[k];
        out[b * NCLS_ + d] = a;
    }
}

extern "C" void kernel_launch(void* const* d_in, const int* in_sizes, int n_in,
                              void* d_out, int out_size)
{
    const float* x    = (const float*)d_in[0];
    const float* Wih1 = (const float*)d_in[1];
    const float* Whh1 = (const float*)d_in[2];
    const float* bih1 = (const float*)d_in[3];
    const float* bhh1 = (const float*)d_in[4];
    const float* Wih2 = (const float*)d_in[5];
    const float* Whh2 = (const float*)d_in[6];
    const float* bih2 = (const float*)d_in[7];
    const float* bhh2 = (const float*)d_in[8];
    const float* W1   = (const float*)d_in[9];
    const float* b1   = (const float*)d_in[10];
    const float* W2   = (const float*)d_in[11];
    const float* b2   = (const float*)d_in[12];

    cudaFuncSetAttribute(lstm_persistent, cudaFuncAttributeMaxDynamicSharedMemorySize, SMEM_BYTES);

    lstm_persistent<<<NG * CPG, NTH, SMEM_BYTES>>>(x, Wih1, Whh1, bih1, bhh1,
                                                   Wih2, Whh2, bih2, bhh2);
    classify_k<<<B_, DMLP_>>>(W1, b1, W2, b2, (float*)d_out);
}